// round 1
// baseline (speedup 1.0000x reference)
#include <cuda_runtime.h>
#include <math.h>

// Problem constants
#define B_    32
#define C1_   128
#define C2_   128
#define KEXP_ 4
#define HH_   96
#define WW_   96
#define HW_   (HH_*WW_)            // 9216
#define WMIX_PER_B (C2_*C1_*9)     // 147456

// ---------------- scratch (device globals; no runtime allocation) -----------
__device__ float g_gap[B_*C1_];
__device__ float g_gate[B_*KEXP_];
__device__ float g_bmix[B_*C2_];
__device__ float g_wmix[B_*WMIX_PER_B];       // ~18 MB
__device__ float g_psum[C2_*B_];
__device__ float g_psq [C2_*B_];
__device__ float g_scale[C2_];
__device__ float g_shift[C2_];

// ---------------- helpers ----------------------------------------------------
__device__ __forceinline__ float warpReduceSum(float v) {
    #pragma unroll
    for (int o = 16; o > 0; o >>= 1) v += __shfl_down_sync(0xffffffffu, v, o);
    return v;
}

// ---------------- 1) global average pool: gap[b,c1] -------------------------
__global__ void gap_kernel(const float* __restrict__ x) {
    int bc = blockIdx.x;                       // b*C1 + c1
    const float* p = x + (long long)bc * HW_;
    float s = 0.f;
    for (int i = threadIdx.x; i < HW_; i += 256) s += p[i];
    s = warpReduceSum(s);
    __shared__ float sm[8];
    int lane = threadIdx.x & 31, w = threadIdx.x >> 5;
    if (lane == 0) sm[w] = s;
    __syncthreads();
    if (w == 0) {
        s = (lane < 8) ? sm[lane] : 0.f;
        s = warpReduceSum(s);
        if (lane == 0) g_gap[bc] = s * (1.0f / (float)HW_);
    }
}

// ---------------- 2) gate softmax + bmix -------------------------------------
__global__ void gate_kernel(const float* __restrict__ fc_w,
                            const float* __restrict__ fc_b,
                            const float* __restrict__ bias) {
    __shared__ float sgate[B_*KEXP_];
    int tid = threadIdx.x;
    if (tid < B_) {
        int b = tid;
        float lg[KEXP_];
        #pragma unroll
        for (int k = 0; k < KEXP_; k++) {
            float s = fc_b[k];
            for (int c = 0; c < C1_; c++) s += g_gap[b*C1_ + c] * fc_w[k*C1_ + c];
            lg[k] = s;
        }
        float m = fmaxf(fmaxf(lg[0], lg[1]), fmaxf(lg[2], lg[3]));
        float e[KEXP_], tot = 0.f;
        #pragma unroll
        for (int k = 0; k < KEXP_; k++) { e[k] = expf(lg[k] - m); tot += e[k]; }
        float inv = 1.0f / tot;
        #pragma unroll
        for (int k = 0; k < KEXP_; k++) {
            float gv = e[k] * inv;
            sgate[b*KEXP_ + k] = gv;
            g_gate[b*KEXP_ + k] = gv;
        }
    }
    __syncthreads();
    for (int i = tid; i < B_*C2_; i += blockDim.x) {
        int b = i >> 7, c2 = i & 127;
        float s = 0.f;
        #pragma unroll
        for (int k = 0; k < KEXP_; k++) s += sgate[b*KEXP_ + k] * bias[k*C2_ + c2];
        g_bmix[i] = s;
    }
}

// ---------------- 3) per-sample weight mix -----------------------------------
__global__ void wmix_kernel(const float* __restrict__ weight) {
    int idx = blockIdx.x * 256 + threadIdx.x;
    if (idx >= B_ * WMIX_PER_B) return;
    int b = idx / WMIX_PER_B;
    int r = idx - b * WMIX_PER_B;
    const float* gp = g_gate + b * KEXP_;
    float v = gp[0] * weight[r]
            + gp[1] * weight[WMIX_PER_B + r]
            + gp[2] * weight[2*WMIX_PER_B + r]
            + gp[3] * weight[3*WMIX_PER_B + r];
    g_wmix[idx] = v;
}

// ---------------- 4) per-sample 3x3 conv (direct, tiled) ---------------------
// Block tile: 16 c2  x  8 h  x  32 w. 256 threads.
// Thread micro-tile: 4 c2 x 4 w. smem x tile padded to 35 cols (conflict-free).
#define TC2 16
#define TH  8
#define TW  32
#define KC  8
__global__ __launch_bounds__(256, 6)
void conv_kernel(const float* __restrict__ x, float* __restrict__ y) {
    __shared__ float xs[KC][TH+2][TW+3];       // 35-col stride
    __shared__ float ws[TC2][KC][9];

    int b   = blockIdx.z >> 3;
    int c2b = (blockIdx.z & 7) * TC2;
    int h0  = blockIdx.y * TH;
    int w0  = blockIdx.x * TW;
    int tid = threadIdx.x;
    int c2g = tid >> 6;            // 0..3  (4 c2 each)
    int sp  = tid & 63;
    int th  = sp >> 3;             // 0..7  row in tile
    int twg = sp & 7;              // 0..7  group of 4 cols

    float acc[4][4] = {};

    const float* xb = x + (long long)(b*C1_) * HW_;
    const float* wb = g_wmix + (long long)(b*C2_ + c2b) * (C1_*9);

    for (int c1c = 0; c1c < C1_; c1c += KC) {
        // stage x tile (with halo, zero-padded)
        for (int i = tid; i < KC*(TH+2)*34; i += 256) {
            int col = i % 34;
            int t   = i / 34;
            int row = t % (TH+2);
            int c1  = t / (TH+2);
            int gh = h0 - 1 + row;
            int gw = w0 - 1 + col;
            float v = 0.f;
            if ((unsigned)gh < (unsigned)HH_ && (unsigned)gw < (unsigned)WW_)
                v = xb[(c1c + c1)*HW_ + gh*WW_ + gw];
            xs[c1][row][col] = v;
        }
        // stage weights
        for (int i = tid; i < TC2*KC*9; i += 256) {
            int r9 = i % 9;
            int t  = i / 9;
            int c1 = t % KC;
            int c2 = t / KC;
            ws[c2][c1][r9] = wb[(c2*C1_ + c1c + c1)*9 + r9];
        }
        __syncthreads();

        #pragma unroll 2
        for (int c1 = 0; c1 < KC; c1++) {
            #pragma unroll
            for (int ky = 0; ky < 3; ky++) {
                float xv[6];
                #pragma unroll
                for (int m = 0; m < 6; m++)
                    xv[m] = xs[c1][th + ky][twg*4 + m];
                #pragma unroll
                for (int kx = 0; kx < 3; kx++) {
                    float w0v = ws[c2g*4+0][c1][ky*3+kx];
                    float w1v = ws[c2g*4+1][c1][ky*3+kx];
                    float w2v = ws[c2g*4+2][c1][ky*3+kx];
                    float w3v = ws[c2g*4+3][c1][ky*3+kx];
                    #pragma unroll
                    for (int j = 0; j < 4; j++) {
                        float xvv = xv[j + kx];
                        acc[0][j] += w0v * xvv;
                        acc[1][j] += w1v * xvv;
                        acc[2][j] += w2v * xvv;
                        acc[3][j] += w3v * xvv;
                    }
                }
            }
        }
        __syncthreads();
    }

    int h = h0 + th, wc = w0 + twg*4;
    #pragma unroll
    for (int i = 0; i < 4; i++) {
        int c2 = c2b + c2g*4 + i;
        float bm = g_bmix[b*C2_ + c2];
        float4 v = make_float4(acc[i][0]+bm, acc[i][1]+bm, acc[i][2]+bm, acc[i][3]+bm);
        *(float4*)&y[((long long)(b*C2_ + c2)*HH_ + h)*WW_ + wc] = v;
    }
}

// ---------------- 5) BN partial stats per (c2, b) ----------------------------
__global__ void bnstat_kernel(const float* __restrict__ y) {
    int c2 = blockIdx.x, b = blockIdx.y;
    const float* p = y + (long long)(b*C2_ + c2) * HW_;
    float s = 0.f, q = 0.f;
    for (int i = threadIdx.x; i < HW_; i += 256) {
        float v = p[i];
        s += v; q += v*v;
    }
    s = warpReduceSum(s); q = warpReduceSum(q);
    __shared__ float sm[8], qm[8];
    int lane = threadIdx.x & 31, w = threadIdx.x >> 5;
    if (lane == 0) { sm[w] = s; qm[w] = q; }
    __syncthreads();
    if (w == 0) {
        s = (lane < 8) ? sm[lane] : 0.f;
        q = (lane < 8) ? qm[lane] : 0.f;
        s = warpReduceSum(s); q = warpReduceSum(q);
        if (lane == 0) { g_psum[c2*B_ + b] = s; g_psq[c2*B_ + b] = q; }
    }
}

// ---------------- 6) finalize BN stats ---------------------------------------
__global__ void bnfin_kernel(const float* __restrict__ gamma,
                             const float* __restrict__ beta) {
    int c2 = threadIdx.x;
    if (c2 >= C2_) return;
    float s = 0.f, q = 0.f;
    #pragma unroll
    for (int b = 0; b < B_; b++) { s += g_psum[c2*B_ + b]; q += g_psq[c2*B_ + b]; }
    const float n = (float)B_ * (float)HW_;
    float mean = s / n;
    float var  = q / n - mean*mean;
    float inv  = rsqrtf(var + 1e-5f);
    float sc = gamma[c2] * inv;
    g_scale[c2] = sc;
    g_shift[c2] = beta[c2] - mean * sc;
}

// ---------------- 7) BN affine + SiLU, in place -------------------------------
__global__ void act_kernel(float* __restrict__ y) {
    int idx = blockIdx.x * 256 + threadIdx.x;   // float4 index
    const int N4 = (B_*C2_*HW_) / 4;            // 9437184
    if (idx >= N4) return;
    int c2 = (idx / (HW_/4)) & (C2_-1);
    float sc = g_scale[c2], sh = g_shift[c2];
    float4 v = ((const float4*)y)[idx];
    float t;
    t = v.x*sc + sh; v.x = t / (1.f + expf(-t));
    t = v.y*sc + sh; v.y = t / (1.f + expf(-t));
    t = v.z*sc + sh; v.z = t / (1.f + expf(-t));
    t = v.w*sc + sh; v.w = t / (1.f + expf(-t));
    ((float4*)y)[idx] = v;
}

// ---------------- launcher ----------------------------------------------------
extern "C" void kernel_launch(void* const* d_in, const int* in_sizes, int n_in,
                              void* d_out, int out_size) {
    const float* x      = (const float*)d_in[0];
    const float* fc_w   = (const float*)d_in[1];
    const float* fc_b   = (const float*)d_in[2];
    const float* weight = (const float*)d_in[3];
    const float* bias   = (const float*)d_in[4];
    const float* gamma  = (const float*)d_in[5];
    const float* beta   = (const float*)d_in[6];
    float* y = (float*)d_out;

    gap_kernel<<<B_*C1_, 256>>>(x);
    gate_kernel<<<1, 128>>>(fc_w, fc_b, bias);
    wmix_kernel<<<(B_*WMIX_PER_B + 255)/256, 256>>>(weight);

    dim3 cgrid(WW_/TW, HH_/TH, B_*(C2_/TC2));   // (3, 12, 256)
    conv_kernel<<<cgrid, 256>>>(x, y);

    dim3 sgrid(C2_, B_);
    bnstat_kernel<<<sgrid, 256>>>(y);
    bnfin_kernel<<<1, 128>>>(gamma, beta);

    const int N4 = (B_*C2_*HW_) / 4;
    act_kernel<<<(N4 + 255)/256, 256>>>(y);
}

// round 2
// speedup vs baseline: 1.0019x; 1.0019x over previous
#include <cuda_runtime.h>
#include <math.h>

// Problem constants
#define B_    32
#define C1_   128
#define C2_   128
#define KEXP_ 4
#define HH_   96
#define WW_   96
#define HW_   (HH_*WW_)            // 9216
#define WMIX_PER_B (C2_*C1_*9)     // 147456

// ---------------- scratch (device globals; no runtime allocation) -----------
__device__ float g_gap[B_*C1_];
__device__ float g_gate[B_*KEXP_];
__device__ float g_bmix[B_*C2_];
__device__ float g_wmix[B_*WMIX_PER_B];       // ~18 MB
__device__ float g_psum[C2_*B_];
__device__ float g_psq [C2_*B_];
__device__ float g_scale[C2_];
__device__ float g_shift[C2_];

// ---------------- helpers ----------------------------------------------------
__device__ __forceinline__ float warpReduceSum(float v) {
    #pragma unroll
    for (int o = 16; o > 0; o >>= 1) v += __shfl_down_sync(0xffffffffu, v, o);
    return v;
}

// ---------------- 1) global average pool: gap[b,c1] -------------------------
__global__ void gap_kernel(const float* __restrict__ x) {
    int bc = blockIdx.x;                       // b*C1 + c1
    const float* p = x + (long long)bc * HW_;
    float s = 0.f;
    for (int i = threadIdx.x; i < HW_; i += 256) s += p[i];
    s = warpReduceSum(s);
    __shared__ float sm[8];
    int lane = threadIdx.x & 31, w = threadIdx.x >> 5;
    if (lane == 0) sm[w] = s;
    __syncthreads();
    if (w == 0) {
        s = (lane < 8) ? sm[lane] : 0.f;
        s = warpReduceSum(s);
        if (lane == 0) g_gap[bc] = s * (1.0f / (float)HW_);
    }
}

// ---------------- 2) gate softmax + bmix -------------------------------------
__global__ void gate_kernel(const float* __restrict__ fc_w,
                            const float* __restrict__ fc_b,
                            const float* __restrict__ bias) {
    __shared__ float sgate[B_*KEXP_];
    int tid = threadIdx.x;
    if (tid < B_) {
        int b = tid;
        float lg[KEXP_];
        #pragma unroll
        for (int k = 0; k < KEXP_; k++) {
            float s = fc_b[k];
            for (int c = 0; c < C1_; c++) s += g_gap[b*C1_ + c] * fc_w[k*C1_ + c];
            lg[k] = s;
        }
        float m = fmaxf(fmaxf(lg[0], lg[1]), fmaxf(lg[2], lg[3]));
        float e[KEXP_], tot = 0.f;
        #pragma unroll
        for (int k = 0; k < KEXP_; k++) { e[k] = expf(lg[k] - m); tot += e[k]; }
        float inv = 1.0f / tot;
        #pragma unroll
        for (int k = 0; k < KEXP_; k++) {
            float gv = e[k] * inv;
            sgate[b*KEXP_ + k] = gv;
            g_gate[b*KEXP_ + k] = gv;
        }
    }
    __syncthreads();
    for (int i = tid; i < B_*C2_; i += blockDim.x) {
        int b = i >> 7, c2 = i & 127;
        float s = 0.f;
        #pragma unroll
        for (int k = 0; k < KEXP_; k++) s += sgate[b*KEXP_ + k] * bias[k*C2_ + c2];
        g_bmix[i] = s;
    }
}

// ---------------- 3) per-sample weight mix -----------------------------------
__global__ void wmix_kernel(const float* __restrict__ weight) {
    int idx = blockIdx.x * 256 + threadIdx.x;
    if (idx >= B_ * WMIX_PER_B) return;
    int b = idx / WMIX_PER_B;
    int r = idx - b * WMIX_PER_B;
    const float* gp = g_gate + b * KEXP_;
    float v = gp[0] * weight[r]
            + gp[1] * weight[WMIX_PER_B + r]
            + gp[2] * weight[2*WMIX_PER_B + r]
            + gp[3] * weight[3*WMIX_PER_B + r];
    g_wmix[idx] = v;
}

// ---------------- 4) per-sample 3x3 conv (direct, tiled) ---------------------
// Block tile: 16 c2  x  8 h  x  32 w. 256 threads.
// Thread micro-tile: 4 c2 x 4 w. smem x tile padded to 35 cols (conflict-free).
#define TC2 16
#define TH  8
#define TW  32
#define KC  8
__global__ __launch_bounds__(256, 6)
void conv_kernel(const float* __restrict__ x, float* __restrict__ y) {
    __shared__ float xs[KC][TH+2][TW+3];       // 35-col stride
    __shared__ float ws[TC2][KC][9];

    int b   = blockIdx.z >> 3;
    int c2b = (blockIdx.z & 7) * TC2;
    int h0  = blockIdx.y * TH;
    int w0  = blockIdx.x * TW;
    int tid = threadIdx.x;
    int c2g = tid >> 6;            // 0..3  (4 c2 each)
    int sp  = tid & 63;
    int th  = sp >> 3;             // 0..7  row in tile
    int twg = sp & 7;              // 0..7  group of 4 cols

    float acc[4][4] = {};

    const float* xb = x + (long long)(b*C1_) * HW_;
    const float* wb = g_wmix + (long long)(b*C2_ + c2b) * (C1_*9);

    for (int c1c = 0; c1c < C1_; c1c += KC) {
        // stage x tile (with halo, zero-padded)
        for (int i = tid; i < KC*(TH+2)*34; i += 256) {
            int col = i % 34;
            int t   = i / 34;
            int row = t % (TH+2);
            int c1  = t / (TH+2);
            int gh = h0 - 1 + row;
            int gw = w0 - 1 + col;
            float v = 0.f;
            if ((unsigned)gh < (unsigned)HH_ && (unsigned)gw < (unsigned)WW_)
                v = xb[(c1c + c1)*HW_ + gh*WW_ + gw];
            xs[c1][row][col] = v;
        }
        // stage weights
        for (int i = tid; i < TC2*KC*9; i += 256) {
            int r9 = i % 9;
            int t  = i / 9;
            int c1 = t % KC;
            int c2 = t / KC;
            ws[c2][c1][r9] = wb[(c2*C1_ + c1c + c1)*9 + r9];
        }
        __syncthreads();

        #pragma unroll 2
        for (int c1 = 0; c1 < KC; c1++) {
            #pragma unroll
            for (int ky = 0; ky < 3; ky++) {
                float xv[6];
                #pragma unroll
                for (int m = 0; m < 6; m++)
                    xv[m] = xs[c1][th + ky][twg*4 + m];
                #pragma unroll
                for (int kx = 0; kx < 3; kx++) {
                    float w0v = ws[c2g*4+0][c1][ky*3+kx];
                    float w1v = ws[c2g*4+1][c1][ky*3+kx];
                    float w2v = ws[c2g*4+2][c1][ky*3+kx];
                    float w3v = ws[c2g*4+3][c1][ky*3+kx];
                    #pragma unroll
                    for (int j = 0; j < 4; j++) {
                        float xvv = xv[j + kx];
                        acc[0][j] += w0v * xvv;
                        acc[1][j] += w1v * xvv;
                        acc[2][j] += w2v * xvv;
                        acc[3][j] += w3v * xvv;
                    }
                }
            }
        }
        __syncthreads();
    }

    int h = h0 + th, wc = w0 + twg*4;
    #pragma unroll
    for (int i = 0; i < 4; i++) {
        int c2 = c2b + c2g*4 + i;
        float bm = g_bmix[b*C2_ + c2];
        float4 v = make_float4(acc[i][0]+bm, acc[i][1]+bm, acc[i][2]+bm, acc[i][3]+bm);
        *(float4*)&y[((long long)(b*C2_ + c2)*HH_ + h)*WW_ + wc] = v;
    }
}

// ---------------- 5) BN partial stats per (c2, b) ----------------------------
__global__ void bnstat_kernel(const float* __restrict__ y) {
    int c2 = blockIdx.x, b = blockIdx.y;
    const float* p = y + (long long)(b*C2_ + c2) * HW_;
    float s = 0.f, q = 0.f;
    for (int i = threadIdx.x; i < HW_; i += 256) {
        float v = p[i];
        s += v; q += v*v;
    }
    s = warpReduceSum(s); q = warpReduceSum(q);
    __shared__ float sm[8], qm[8];
    int lane = threadIdx.x & 31, w = threadIdx.x >> 5;
    if (lane == 0) { sm[w] = s; qm[w] = q; }
    __syncthreads();
    if (w == 0) {
        s = (lane < 8) ? sm[lane] : 0.f;
        q = (lane < 8) ? qm[lane] : 0.f;
        s = warpReduceSum(s); q = warpReduceSum(q);
        if (lane == 0) { g_psum[c2*B_ + b] = s; g_psq[c2*B_ + b] = q; }
    }
}

// ---------------- 6) finalize BN stats ---------------------------------------
__global__ void bnfin_kernel(const float* __restrict__ gamma,
                             const float* __restrict__ beta) {
    int c2 = threadIdx.x;
    if (c2 >= C2_) return;
    float s = 0.f, q = 0.f;
    #pragma unroll
    for (int b = 0; b < B_; b++) { s += g_psum[c2*B_ + b]; q += g_psq[c2*B_ + b]; }
    const float n = (float)B_ * (float)HW_;
    float mean = s / n;
    float var  = q / n - mean*mean;
    float inv  = rsqrtf(var + 1e-5f);
    float sc = gamma[c2] * inv;
    g_scale[c2] = sc;
    g_shift[c2] = beta[c2] - mean * sc;
}

// ---------------- 7) BN affine + SiLU, in place -------------------------------
__global__ void act_kernel(float* __restrict__ y) {
    int idx = blockIdx.x * 256 + threadIdx.x;   // float4 index
    const int N4 = (B_*C2_*HW_) / 4;            // 9437184
    if (idx >= N4) return;
    int c2 = (idx / (HW_/4)) & (C2_-1);
    float sc = g_scale[c2], sh = g_shift[c2];
    float4 v = ((const float4*)y)[idx];
    float t;
    t = v.x*sc + sh; v.x = t / (1.f + expf(-t));
    t = v.y*sc + sh; v.y = t / (1.f + expf(-t));
    t = v.z*sc + sh; v.z = t / (1.f + expf(-t));
    t = v.w*sc + sh; v.w = t / (1.f + expf(-t));
    ((float4*)y)[idx] = v;
}

// ---------------- launcher ----------------------------------------------------
extern "C" void kernel_launch(void* const* d_in, const int* in_sizes, int n_in,
                              void* d_out, int out_size) {
    const float* x      = (const float*)d_in[0];
    const float* fc_w   = (const float*)d_in[1];
    const float* fc_b   = (const float*)d_in[2];
    const float* weight = (const float*)d_in[3];
    const float* bias   = (const float*)d_in[4];
    const float* gamma  = (const float*)d_in[5];
    const float* beta   = (const float*)d_in[6];
    float* y = (float*)d_out;

    gap_kernel<<<B_*C1_, 256>>>(x);
    gate_kernel<<<1, 128>>>(fc_w, fc_b, bias);
    wmix_kernel<<<(B_*WMIX_PER_B + 255)/256, 256>>>(weight);

    dim3 cgrid(WW_/TW, HH_/TH, B_*(C2_/TC2));   // (3, 12, 256)
    conv_kernel<<<cgrid, 256>>>(x, y);

    dim3 sgrid(C2_, B_);
    bnstat_kernel<<<sgrid, 256>>>(y);
    bnfin_kernel<<<1, 128>>>(gamma, beta);

    const int N4 = (B_*C2_*HW_) / 4;
    act_kernel<<<(N4 + 255)/256, 256>>>(y);
}

// round 4
// speedup vs baseline: 2.7055x; 2.7004x over previous
#include <cuda_runtime.h>
#include <math.h>
#include <stdint.h>

#define B_    32
#define C1_   128
#define C2_   128
#define KEXP_ 4
#define HH_   96
#define WW_   96
#define HW_   (HH_*WW_)

// ---------------- scratch (device globals) -----------------------------------
__device__ float g_gap[B_*C1_];
__device__ float g_gate[B_*KEXP_];
__device__ float g_bmix[B_*C2_];
__device__ float g_wmix[(size_t)B_*9*C2_*C1_];      // [b][tap][c2][c1] tf32
__device__ float g_xT[(size_t)B_*HH_*WW_*C1_];      // [b][h][w][c1]    tf32
__device__ float g_psum[C2_*B_];
__device__ float g_psq [C2_*B_];
__device__ float g_scale[C2_];
__device__ float g_shift[C2_];

// ---------------- helpers -------------------------------------------------------
__device__ __forceinline__ float to_tf32(float f) {
    uint32_t u;
    asm("cvt.rna.tf32.f32 %0, %1;" : "=r"(u) : "f"(f));
    return __uint_as_float(u);
}
__device__ __forceinline__ float warpReduceSum(float v) {
    #pragma unroll
    for (int o = 16; o > 0; o >>= 1) v += __shfl_down_sync(0xffffffffu, v, o);
    return v;
}
__device__ __forceinline__ void mma_tf32(float* d, const uint32_t* a, const uint32_t* b) {
    asm volatile(
        "mma.sync.aligned.m16n8k8.row.col.f32.tf32.tf32.f32 "
        "{%0,%1,%2,%3}, {%4,%5,%6,%7}, {%8,%9}, {%0,%1,%2,%3};"
        : "+f"(d[0]), "+f"(d[1]), "+f"(d[2]), "+f"(d[3])
        : "r"(a[0]), "r"(a[1]), "r"(a[2]), "r"(a[3]), "r"(b[0]), "r"(b[1]));
}

// ---------------- 1) GAP ----------------------------------------------------------
__global__ void gap_kernel(const float* __restrict__ x) {
    int bc = blockIdx.x;
    const float* p = x + (size_t)bc * HW_;
    float s = 0.f;
    for (int i = threadIdx.x; i < HW_; i += 256) s += p[i];
    s = warpReduceSum(s);
    __shared__ float sm[8];
    int lane = threadIdx.x & 31, w = threadIdx.x >> 5;
    if (lane == 0) sm[w] = s;
    __syncthreads();
    if (w == 0) {
        s = (lane < 8) ? sm[lane] : 0.f;
        s = warpReduceSum(s);
        if (lane == 0) g_gap[bc] = s * (1.0f / (float)HW_);
    }
}

// ---------------- 2) gating + bias mix ---------------------------------------------
__global__ void gate_kernel(const float* __restrict__ fc_w,
                            const float* __restrict__ fc_b,
                            const float* __restrict__ bias) {
    __shared__ float sgate[B_*KEXP_];
    int tid = threadIdx.x;
    if (tid < B_) {
        int b = tid;
        float lg[KEXP_];
        #pragma unroll
        for (int k = 0; k < KEXP_; k++) {
            float s = fc_b[k];
            for (int c = 0; c < C1_; c++) s += g_gap[b*C1_ + c] * fc_w[k*C1_ + c];
            lg[k] = s;
        }
        float m = fmaxf(fmaxf(lg[0], lg[1]), fmaxf(lg[2], lg[3]));
        float e[KEXP_], tot = 0.f;
        #pragma unroll
        for (int k = 0; k < KEXP_; k++) { e[k] = expf(lg[k] - m); tot += e[k]; }
        float inv = 1.0f / tot;
        #pragma unroll
        for (int k = 0; k < KEXP_; k++) {
            float gv = e[k] * inv;
            sgate[b*KEXP_ + k] = gv;
            g_gate[b*KEXP_ + k] = gv;
        }
    }
    __syncthreads();
    for (int i = tid; i < B_*C2_; i += blockDim.x) {
        int b = i >> 7, c2 = i & 127;
        float s = 0.f;
        #pragma unroll
        for (int k = 0; k < KEXP_; k++) s += sgate[b*KEXP_ + k] * bias[k*C2_ + c2];
        g_bmix[i] = s;
    }
}

// ---------------- 3) weight mix -> [b][tap][c2][c1] (tf32) --------------------------
__global__ void wmix_kernel(const float* __restrict__ weight) {
    int c2 = blockIdx.x, b = blockIdx.y;
    int c1 = threadIdx.x;
    __shared__ float sg[KEXP_];
    if (threadIdx.x < KEXP_) sg[threadIdx.x] = g_gate[b*KEXP_ + threadIdx.x];
    __syncthreads();
    float acc[9] = {0,0,0,0,0,0,0,0,0};
    #pragma unroll
    for (int k = 0; k < KEXP_; k++) {
        const float* wp = weight + (((size_t)k*C2_ + c2)*C1_ + c1)*9;
        float g = sg[k];
        #pragma unroll
        for (int r = 0; r < 9; r++) acc[r] += g * wp[r];
    }
    #pragma unroll
    for (int r = 0; r < 9; r++)
        g_wmix[(((size_t)b*9 + r)*C2_ + c2)*C1_ + c1] = to_tf32(acc[r]);
}

// ---------------- 4) x transpose -> [b][h][w][c1] (tf32) ----------------------------
__global__ void xT_kernel(const float* __restrict__ x) {
    __shared__ float sm[128][33];
    int wblk = blockIdx.x, h = blockIdx.y, b = blockIdx.z;
    int tid = threadIdx.x;
    #pragma unroll
    for (int p = 0; p < 16; p++) {
        int c1 = p*8 + (tid >> 5);
        int j  = tid & 31;
        sm[c1][j] = x[(((size_t)b*C1_ + c1)*HH_ + h)*WW_ + wblk*32 + j];
    }
    __syncthreads();
    #pragma unroll
    for (int p = 0; p < 16; p++) {
        int c1 = tid & 127;
        int j  = p*2 + (tid >> 7);
        g_xT[((((size_t)b*HH_ + h)*WW_) + wblk*32 + j)*C1_ + c1] = to_tf32(sm[c1][j]);
    }
}

// ---------------- 5) conv via mma.sync tf32 -----------------------------------------
// CTA = (h, b). M=128 c2 x N=96 w, K = 9 taps x 128 c1.
// 8 warps: (warp>>2) -> M half (64), (warp&3) -> N quarter (24).
// smem: A tile 128x32 (stride 36), B row 98x128 (stride 132).
#define ASTRIDE 36
#define BSTRIDE 132
#define SA_FLOATS (128*ASTRIDE)          // 4608
#define SB_FLOATS (98*BSTRIDE)           // 12936
#define CONV_SMEM ((SA_FLOATS + SB_FLOATS) * 4)

__global__ void __launch_bounds__(256, 2)
conv_mma_kernel(float* __restrict__ y) {
    extern __shared__ float sh[];
    float* sA = sh;                 // [c2][k] stride 36
    float* sB = sh + SA_FLOATS;     // [col 0..97][c1] stride 132 ; col c = input w (c-1)

    int tid  = threadIdx.x;
    int lane = tid & 31;
    int warp = tid >> 5;
    int h = blockIdx.x, b = blockIdx.y;
    int mbase = (warp >> 2) * 64;
    int nbase = (warp & 3) * 24;
    int gq = lane >> 2;             // groupID 0..7
    int tg = lane & 3;              // threadID_in_group 0..3

    float d[4][3][4];
    #pragma unroll
    for (int mi = 0; mi < 4; mi++)
        #pragma unroll
        for (int ni = 0; ni < 3; ni++)
            #pragma unroll
            for (int q = 0; q < 4; q++) d[mi][ni][q] = 0.f;

    for (int dy = 0; dy < 3; dy++) {
        __syncthreads();            // protect sB from readers of previous dy
        // stage input row h+dy-1 (all 128 c1), cols -1..96 zero-padded
        {
            int gh = h + dy - 1;
            for (int i = tid; i < 98*32; i += 256) {
                int col = i >> 5, e = i & 31;
                int gw = col - 1;
                float4 v = make_float4(0.f, 0.f, 0.f, 0.f);
                if ((unsigned)gh < (unsigned)HH_ && (unsigned)gw < (unsigned)WW_)
                    v = *(const float4*)(g_xT + (((size_t)b*HH_ + gh)*WW_ + gw)*C1_ + e*4);
                *(float4*)&sB[col*BSTRIDE + e*4] = v;
            }
        }
        for (int dx = 0; dx < 3; dx++) {
            int tap = dy*3 + dx;
            const float* wsrc = g_wmix + ((size_t)b*9 + tap)*C2_*C1_;
            for (int c1i = 0; c1i < 4; c1i++) {
                int c1c = c1i * 32;
                __syncthreads();    // protect sA (and first pass: fence sB writes)
                for (int i = tid; i < 128*8; i += 256) {
                    int c2 = i >> 3, e = i & 7;
                    float4 v = *(const float4*)(wsrc + (size_t)c2*C1_ + c1c + e*4);
                    *(float4*)&sA[c2*ASTRIDE + e*4] = v;
                }
                __syncthreads();

                #pragma unroll
                for (int ks = 0; ks < 4; ks++) {
                    int k0 = ks * 8;
                    uint32_t a[4][4];
                    #pragma unroll
                    for (int mi = 0; mi < 4; mi++) {
                        int r = mbase + mi*16 + gq;
                        a[mi][0] = __float_as_uint(sA[ r     *ASTRIDE + k0 + tg    ]);
                        a[mi][1] = __float_as_uint(sA[(r + 8)*ASTRIDE + k0 + tg    ]);
                        a[mi][2] = __float_as_uint(sA[ r     *ASTRIDE + k0 + tg + 4]);
                        a[mi][3] = __float_as_uint(sA[(r + 8)*ASTRIDE + k0 + tg + 4]);
                    }
                    uint32_t bb[3][2];
                    #pragma unroll
                    for (int ni = 0; ni < 3; ni++) {
                        int cIn = nbase + ni*8 + gq + dx;   // sB col = outCol + dx
                        int kk  = c1c + k0 + tg;
                        bb[ni][0] = __float_as_uint(sB[cIn*BSTRIDE + kk    ]);
                        bb[ni][1] = __float_as_uint(sB[cIn*BSTRIDE + kk + 4]);
                    }
                    #pragma unroll
                    for (int mi = 0; mi < 4; mi++)
                        #pragma unroll
                        for (int ni = 0; ni < 3; ni++)
                            mma_tf32(d[mi][ni], a[mi], bb[ni]);
                }
            }
        }
    }

    // epilogue: + bmix, store
    #pragma unroll
    for (int mi = 0; mi < 4; mi++) {
        int c2a = mbase + mi*16 + gq;
        int c2b = c2a + 8;
        float bm0 = g_bmix[b*C2_ + c2a];
        float bm1 = g_bmix[b*C2_ + c2b];
        float* rowa = y + (((size_t)b*C2_ + c2a)*HH_ + h)*WW_;
        float* rowb = y + (((size_t)b*C2_ + c2b)*HH_ + h)*WW_;
        #pragma unroll
        for (int ni = 0; ni < 3; ni++) {
            int col = nbase + ni*8 + 2*tg;
            float2 v0 = make_float2(d[mi][ni][0] + bm0, d[mi][ni][1] + bm0);
            float2 v1 = make_float2(d[mi][ni][2] + bm1, d[mi][ni][3] + bm1);
            *(float2*)(rowa + col) = v0;
            *(float2*)(rowb + col) = v1;
        }
    }
}

// ---------------- 6) BN partial stats -------------------------------------------------
__global__ void bnstat_kernel(const float* __restrict__ y) {
    int c2 = blockIdx.x, b = blockIdx.y;
    const float* p = y + ((size_t)b*C2_ + c2) * HW_;
    float s = 0.f, q = 0.f;
    for (int i = threadIdx.x; i < HW_; i += 256) {
        float v = p[i];
        s += v; q += v*v;
    }
    s = warpReduceSum(s); q = warpReduceSum(q);
    __shared__ float sms[8], smq[8];
    int lane = threadIdx.x & 31, w = threadIdx.x >> 5;
    if (lane == 0) { sms[w] = s; smq[w] = q; }
    __syncthreads();
    if (w == 0) {
        s = (lane < 8) ? sms[lane] : 0.f;
        q = (lane < 8) ? smq[lane] : 0.f;
        s = warpReduceSum(s); q = warpReduceSum(q);
        if (lane == 0) { g_psum[c2*B_ + b] = s; g_psq[c2*B_ + b] = q; }
    }
}

// ---------------- 7) finalize BN --------------------------------------------------------
__global__ void bnfin_kernel(const float* __restrict__ gamma,
                             const float* __restrict__ beta) {
    int c2 = threadIdx.x;
    if (c2 >= C2_) return;
    float s = 0.f, q = 0.f;
    #pragma unroll
    for (int b = 0; b < B_; b++) { s += g_psum[c2*B_ + b]; q += g_psq[c2*B_ + b]; }
    const float n = (float)B_ * (float)HW_;
    float mean = s / n;
    float var  = q / n - mean*mean;
    float inv  = rsqrtf(var + 1e-5f);
    float sc = gamma[c2] * inv;
    g_scale[c2] = sc;
    g_shift[c2] = beta[c2] - mean * sc;
}

// ---------------- 8) BN affine + SiLU ----------------------------------------------------
__global__ void act_kernel(float* __restrict__ y) {
    int idx = blockIdx.x * 256 + threadIdx.x;
    const int N4 = (B_*C2_*HW_) / 4;
    if (idx >= N4) return;
    int c2 = (idx / (HW_/4)) & (C2_-1);
    float sc = g_scale[c2], sh = g_shift[c2];
    float4 v = ((const float4*)y)[idx];
    float t;
    t = v.x*sc + sh; v.x = t / (1.f + expf(-t));
    t = v.y*sc + sh; v.y = t / (1.f + expf(-t));
    t = v.z*sc + sh; v.z = t / (1.f + expf(-t));
    t = v.w*sc + sh; v.w = t / (1.f + expf(-t));
    ((float4*)y)[idx] = v;
}

// ---------------- launcher -----------------------------------------------------------------
extern "C" void kernel_launch(void* const* d_in, const int* in_sizes, int n_in,
                              void* d_out, int out_size) {
    const float* x      = (const float*)d_in[0];
    const float* fc_w   = (const float*)d_in[1];
    const float* fc_b   = (const float*)d_in[2];
    const float* weight = (const float*)d_in[3];
    const float* bias   = (const float*)d_in[4];
    const float* gamma  = (const float*)d_in[5];
    const float* beta   = (const float*)d_in[6];
    float* y = (float*)d_out;

    cudaFuncSetAttribute(conv_mma_kernel,
                         cudaFuncAttributeMaxDynamicSharedMemorySize, CONV_SMEM);

    gap_kernel<<<B_*C1_, 256>>>(x);
    gate_kernel<<<1, 128>>>(fc_w, fc_b, bias);

    dim3 wgrid(C2_, B_);
    wmix_kernel<<<wgrid, 128>>>(weight);

    dim3 tgrid(WW_/32, HH_, B_);
    xT_kernel<<<tgrid, 256>>>(x);

    dim3 cgrid(HH_, B_);
    conv_mma_kernel<<<cgrid, 256, CONV_SMEM>>>(y);

    dim3 sgrid(C2_, B_);
    bnstat_kernel<<<sgrid, 256>>>(y);
    bnfin_kernel<<<1, 128>>>(gamma, beta);

    const int N4 = (B_*C2_*HW_) / 4;
    act_kernel<<<(N4 + 255)/256, 256>>>(y);
}

// round 5
// speedup vs baseline: 5.2705x; 1.9481x over previous
#include <cuda_runtime.h>
#include <cuda_fp16.h>
#include <math.h>
#include <stdint.h>

#define B_    32
#define C1_   128
#define C2_   128
#define KEXP_ 4
#define HH_   96
#define WW_   96
#define HW_   (HH_*WW_)

// ---------------- scratch (device globals) -----------------------------------
__device__ float g_gap[B_*C1_];
__device__ float g_gate[B_*KEXP_];
__device__ float g_bmix[B_*C2_];
__device__ __half g_wh[(size_t)B_*9*C2_*C1_];       // [b][tap][c2][c1] fp16
__device__ __half g_xh[(size_t)B_*HH_*WW_*C1_];     // [b][h][w][c1]    fp16
__device__ float g_psum[C2_*B_];
__device__ float g_psq [C2_*B_];
__device__ float g_scale[C2_];
__device__ float g_shift[C2_];

// ---------------- helpers -------------------------------------------------------
__device__ __forceinline__ float warpReduceSum(float v) {
    #pragma unroll
    for (int o = 16; o > 0; o >>= 1) v += __shfl_down_sync(0xffffffffu, v, o);
    return v;
}
__device__ __forceinline__ void mma_f16(float* d, const uint32_t* a, const uint32_t* b) {
    asm volatile(
        "mma.sync.aligned.m16n8k16.row.col.f32.f16.f16.f32 "
        "{%0,%1,%2,%3}, {%4,%5,%6,%7}, {%8,%9}, {%0,%1,%2,%3};"
        : "+f"(d[0]), "+f"(d[1]), "+f"(d[2]), "+f"(d[3])
        : "r"(a[0]), "r"(a[1]), "r"(a[2]), "r"(a[3]), "r"(b[0]), "r"(b[1]));
}

// ---------------- 1) GAP ----------------------------------------------------------
__global__ void gap_kernel(const float* __restrict__ x) {
    int bc = blockIdx.x;
    const float* p = x + (size_t)bc * HW_;
    float s = 0.f;
    for (int i = threadIdx.x; i < HW_; i += 256) s += p[i];
    s = warpReduceSum(s);
    __shared__ float sm[8];
    int lane = threadIdx.x & 31, w = threadIdx.x >> 5;
    if (lane == 0) sm[w] = s;
    __syncthreads();
    if (w == 0) {
        s = (lane < 8) ? sm[lane] : 0.f;
        s = warpReduceSum(s);
        if (lane == 0) g_gap[bc] = s * (1.0f / (float)HW_);
    }
}

// ---------------- 2) gating + bias mix ---------------------------------------------
__global__ void gate_kernel(const float* __restrict__ fc_w,
                            const float* __restrict__ fc_b,
                            const float* __restrict__ bias) {
    __shared__ float sgate[B_*KEXP_];
    int tid = threadIdx.x;
    if (tid < B_) {
        int b = tid;
        float lg[KEXP_];
        #pragma unroll
        for (int k = 0; k < KEXP_; k++) {
            float s = fc_b[k];
            for (int c = 0; c < C1_; c++) s += g_gap[b*C1_ + c] * fc_w[k*C1_ + c];
            lg[k] = s;
        }
        float m = fmaxf(fmaxf(lg[0], lg[1]), fmaxf(lg[2], lg[3]));
        float e[KEXP_], tot = 0.f;
        #pragma unroll
        for (int k = 0; k < KEXP_; k++) { e[k] = expf(lg[k] - m); tot += e[k]; }
        float inv = 1.0f / tot;
        #pragma unroll
        for (int k = 0; k < KEXP_; k++) {
            float gv = e[k] * inv;
            sgate[b*KEXP_ + k] = gv;
            g_gate[b*KEXP_ + k] = gv;
        }
    }
    __syncthreads();
    for (int i = tid; i < B_*C2_; i += blockDim.x) {
        int b = i >> 7, c2 = i & 127;
        float s = 0.f;
        #pragma unroll
        for (int k = 0; k < KEXP_; k++) s += sgate[b*KEXP_ + k] * bias[k*C2_ + c2];
        g_bmix[i] = s;
    }
}

// ---------------- 3) weight mix -> [b][tap][c2][c1] (fp16) --------------------------
__global__ void wmix_kernel(const float* __restrict__ weight) {
    int c2 = blockIdx.x, b = blockIdx.y;
    int c1 = threadIdx.x;
    __shared__ float sg[KEXP_];
    if (threadIdx.x < KEXP_) sg[threadIdx.x] = g_gate[b*KEXP_ + threadIdx.x];
    __syncthreads();
    float acc[9] = {0,0,0,0,0,0,0,0,0};
    #pragma unroll
    for (int k = 0; k < KEXP_; k++) {
        const float* wp = weight + (((size_t)k*C2_ + c2)*C1_ + c1)*9;
        float g = sg[k];
        #pragma unroll
        for (int r = 0; r < 9; r++) acc[r] += g * wp[r];
    }
    #pragma unroll
    for (int r = 0; r < 9; r++)
        g_wh[(((size_t)b*9 + r)*C2_ + c2)*C1_ + c1] = __float2half_rn(acc[r]);
}

// ---------------- 4) x transpose -> [b][h][w][c1] (fp16) ----------------------------
__global__ void xT_kernel(const float* __restrict__ x) {
    __shared__ float sm[128][33];
    int wblk = blockIdx.x, h = blockIdx.y, b = blockIdx.z;
    int tid = threadIdx.x;
    #pragma unroll
    for (int p = 0; p < 16; p++) {
        int c1 = p*8 + (tid >> 5);
        int j  = tid & 31;
        sm[c1][j] = x[(((size_t)b*C1_ + c1)*HH_ + h)*WW_ + wblk*32 + j];
    }
    __syncthreads();
    #pragma unroll
    for (int p = 0; p < 16; p++) {
        int c1 = tid & 127;
        int j  = p*2 + (tid >> 7);
        g_xh[((((size_t)b*HH_ + h)*WW_) + wblk*32 + j)*C1_ + c1] =
            __float2half_rn(sm[c1][j]);
    }
}

// ---------------- 5) conv via mma.sync fp16 m16n8k16 --------------------------------
// CTA = (h, b). M=128 c2 x N=96 w, K = 9 taps x 128 c1.
// 8 warps: (warp>>2) -> M half (64), (warp&3) -> N quarter (24).
// smem (halves): sA [c2(128)][k(128) pad 136], sB [col(98)][c1(128) pad 136].
#define APAD 136
#define BPAD 136
#define SA_H (128*APAD)              // 17408 halves = 34816 B
#define SB_H (98*BPAD)               // 13328 halves = 26656 B
#define CONV_SMEM ((SA_H + SB_H) * 2)

__global__ void __launch_bounds__(256, 2)
conv_mma_kernel(float* __restrict__ y) {
    extern __shared__ __half sh[];
    __half* sA = sh;                 // [c2][k]
    __half* sB = sh + SA_H;          // [col 0..97][c1]; col c = input w (c-1)

    int tid  = threadIdx.x;
    int lane = tid & 31;
    int warp = tid >> 5;
    int h = blockIdx.x, b = blockIdx.y;
    int mbase = (warp >> 2) * 64;
    int nbase = (warp & 3) * 24;
    int gq = lane >> 2;              // groupID 0..7
    int tg = lane & 3;               // threadID_in_group 0..3

    float d[4][3][4];
    #pragma unroll
    for (int mi = 0; mi < 4; mi++)
        #pragma unroll
        for (int ni = 0; ni < 3; ni++)
            #pragma unroll
            for (int q = 0; q < 4; q++) d[mi][ni][q] = 0.f;

    for (int dy = 0; dy < 3; dy++) {
        __syncthreads();             // protect sB from readers of previous dy
        // stage input row h+dy-1 (128 c1 halves per col), cols -1..96 zero-padded
        {
            int gh = h + dy - 1;
            bool hok = (unsigned)gh < (unsigned)HH_;
            const __half* src = g_xh + (((size_t)b*HH_ + (hok ? gh : 0))*WW_)*C1_;
            for (int i = tid; i < 98*16; i += 256) {
                int col = i >> 4, e = i & 15;
                int gw = col - 1;
                uint4 v = make_uint4(0u, 0u, 0u, 0u);
                if (hok && (unsigned)gw < (unsigned)WW_)
                    v = *(const uint4*)(src + (size_t)gw*C1_ + e*8);
                *(uint4*)(sB + col*BPAD + e*8) = v;
            }
        }
        for (int dx = 0; dx < 3; dx++) {
            int tap = dy*3 + dx;
            const __half* wsrc = g_wh + ((size_t)b*9 + tap)*C2_*C1_;
            __syncthreads();         // protect sA; also fences sB writes on dx==0
            for (int i = tid; i < 128*16; i += 256) {
                int c2 = i >> 4, e = i & 15;
                uint4 v = *(const uint4*)(wsrc + (size_t)c2*C1_ + e*8);
                *(uint4*)(sA + c2*APAD + e*8) = v;
            }
            __syncthreads();

            #pragma unroll
            for (int ks = 0; ks < 8; ks++) {
                int k0 = ks * 16;
                uint32_t a[4][4];
                #pragma unroll
                for (int mi = 0; mi < 4; mi++) {
                    int r = mbase + mi*16 + gq;
                    const __half* pa0 = sA +  r     *APAD + k0 + 2*tg;
                    const __half* pa1 = sA + (r + 8)*APAD + k0 + 2*tg;
                    a[mi][0] = *(const uint32_t*)(pa0);
                    a[mi][1] = *(const uint32_t*)(pa1);
                    a[mi][2] = *(const uint32_t*)(pa0 + 8);
                    a[mi][3] = *(const uint32_t*)(pa1 + 8);
                }
                uint32_t bb[3][2];
                #pragma unroll
                for (int ni = 0; ni < 3; ni++) {
                    int cIn = nbase + ni*8 + gq + dx;   // sB col = outCol + dx
                    const __half* pb = sB + cIn*BPAD + k0 + 2*tg;
                    bb[ni][0] = *(const uint32_t*)(pb);
                    bb[ni][1] = *(const uint32_t*)(pb + 8);
                }
                #pragma unroll
                for (int mi = 0; mi < 4; mi++)
                    #pragma unroll
                    for (int ni = 0; ni < 3; ni++)
                        mma_f16(d[mi][ni], a[mi], bb[ni]);
            }
        }
    }

    // epilogue: + bmix, store
    #pragma unroll
    for (int mi = 0; mi < 4; mi++) {
        int c2a = mbase + mi*16 + gq;
        int c2b = c2a + 8;
        float bm0 = g_bmix[b*C2_ + c2a];
        float bm1 = g_bmix[b*C2_ + c2b];
        float* rowa = y + (((size_t)b*C2_ + c2a)*HH_ + h)*WW_;
        float* rowb = y + (((size_t)b*C2_ + c2b)*HH_ + h)*WW_;
        #pragma unroll
        for (int ni = 0; ni < 3; ni++) {
            int col = nbase + ni*8 + 2*tg;
            float2 v0 = make_float2(d[mi][ni][0] + bm0, d[mi][ni][1] + bm0);
            float2 v1 = make_float2(d[mi][ni][2] + bm1, d[mi][ni][3] + bm1);
            *(float2*)(rowa + col) = v0;
            *(float2*)(rowb + col) = v1;
        }
    }
}

// ---------------- 6) BN partial stats -------------------------------------------------
__global__ void bnstat_kernel(const float* __restrict__ y) {
    int c2 = blockIdx.x, b = blockIdx.y;
    const float* p = y + ((size_t)b*C2_ + c2) * HW_;
    float s = 0.f, q = 0.f;
    for (int i = threadIdx.x; i < HW_; i += 256) {
        float v = p[i];
        s += v; q += v*v;
    }
    s = warpReduceSum(s); q = warpReduceSum(q);
    __shared__ float sms[8], smq[8];
    int lane = threadIdx.x & 31, w = threadIdx.x >> 5;
    if (lane == 0) { sms[w] = s; smq[w] = q; }
    __syncthreads();
    if (w == 0) {
        s = (lane < 8) ? sms[lane] : 0.f;
        q = (lane < 8) ? smq[lane] : 0.f;
        s = warpReduceSum(s); q = warpReduceSum(q);
        if (lane == 0) { g_psum[c2*B_ + b] = s; g_psq[c2*B_ + b] = q; }
    }
}

// ---------------- 7) finalize BN --------------------------------------------------------
__global__ void bnfin_kernel(const float* __restrict__ gamma,
                             const float* __restrict__ beta) {
    int c2 = threadIdx.x;
    if (c2 >= C2_) return;
    float s = 0.f, q = 0.f;
    #pragma unroll
    for (int b = 0; b < B_; b++) { s += g_psum[c2*B_ + b]; q += g_psq[c2*B_ + b]; }
    const float n = (float)B_ * (float)HW_;
    float mean = s / n;
    float var  = q / n - mean*mean;
    float inv  = rsqrtf(var + 1e-5f);
    float sc = gamma[c2] * inv;
    g_scale[c2] = sc;
    g_shift[c2] = beta[c2] - mean * sc;
}

// ---------------- 8) BN affine + SiLU ----------------------------------------------------
__global__ void act_kernel(float* __restrict__ y) {
    int idx = blockIdx.x * 256 + threadIdx.x;
    const int N4 = (B_*C2_*HW_) / 4;
    if (idx >= N4) return;
    int c2 = (idx / (HW_/4)) & (C2_-1);
    float sc = g_scale[c2], sh = g_shift[c2];
    float4 v = ((const float4*)y)[idx];
    float t;
    t = v.x*sc + sh; v.x = t / (1.f + expf(-t));
    t = v.y*sc + sh; v.y = t / (1.f + expf(-t));
    t = v.z*sc + sh; v.z = t / (1.f + expf(-t));
    t = v.w*sc + sh; v.w = t / (1.f + expf(-t));
    ((float4*)y)[idx] = v;
}

// ---------------- launcher -----------------------------------------------------------------
extern "C" void kernel_launch(void* const* d_in, const int* in_sizes, int n_in,
                              void* d_out, int out_size) {
    const float* x      = (const float*)d_in[0];
    const float* fc_w   = (const float*)d_in[1];
    const float* fc_b   = (const float*)d_in[2];
    const float* weight = (const float*)d_in[3];
    const float* bias   = (const float*)d_in[4];
    const float* gamma  = (const float*)d_in[5];
    const float* beta   = (const float*)d_in[6];
    float* y = (float*)d_out;

    cudaFuncSetAttribute(conv_mma_kernel,
                         cudaFuncAttributeMaxDynamicSharedMemorySize, CONV_SMEM);

    gap_kernel<<<B_*C1_, 256>>>(x);
    gate_kernel<<<1, 128>>>(fc_w, fc_b, bias);

    dim3 wgrid(C2_, B_);
    wmix_kernel<<<wgrid, 128>>>(weight);

    dim3 tgrid(WW_/32, HH_, B_);
    xT_kernel<<<tgrid, 256>>>(x);

    dim3 cgrid(HH_, B_);
    conv_mma_kernel<<<cgrid, 256, CONV_SMEM>>>(y);

    dim3 sgrid(C2_, B_);
    bnstat_kernel<<<sgrid, 256>>>(y);
    bnfin_kernel<<<1, 128>>>(gamma, beta);

    const int N4 = (B_*C2_*HW_) / 4;
    act_kernel<<<(N4 + 255)/256, 256>>>(y);
}

// round 7
// speedup vs baseline: 6.9395x; 1.3167x over previous
#include <cuda_runtime.h>
#include <cuda_fp16.h>
#include <math.h>
#include <stdint.h>

#define B_    32
#define C1_   128
#define C2_   128
#define KEXP_ 4
#define HH_   96
#define WW_   96
#define HW_   (HH_*WW_)

// ---------------- scratch (device globals) -----------------------------------
__device__ float g_gate[B_*KEXP_];
__device__ float g_bmix[B_*C2_];
__device__ __half g_wh[(size_t)B_*9*C2_*C1_];       // [b][tap][c2][c1] fp16
__device__ __half g_xh[(size_t)B_*HH_*WW_*C1_];     // [b][h][w][c1]    fp16
__device__ float g_gpart[(size_t)B_*288*C1_];       // gap partials
__device__ float g_bnpart[(size_t)B_*24*C2_*2];     // BN partials per (b,hg)
__device__ float g_scale[C2_];
__device__ float g_shift[C2_];

// ---------------- helpers -------------------------------------------------------
__device__ __forceinline__ uint32_t smem_u32(const void* p) {
    uint32_t a;
    asm("{ .reg .u64 t; cvta.to.shared.u64 t, %1; cvt.u32.u64 %0, t; }" : "=r"(a) : "l"(p));
    return a;
}
__device__ __forceinline__ float warpReduceSum(float v) {
    #pragma unroll
    for (int o = 16; o > 0; o >>= 1) v += __shfl_down_sync(0xffffffffu, v, o);
    return v;
}
__device__ __forceinline__ void mma_f16(float* d, const uint32_t* a, const uint32_t* b) {
    asm volatile(
        "mma.sync.aligned.m16n8k16.row.col.f32.f16.f16.f32 "
        "{%0,%1,%2,%3}, {%4,%5,%6,%7}, {%8,%9}, {%0,%1,%2,%3};"
        : "+f"(d[0]), "+f"(d[1]), "+f"(d[2]), "+f"(d[3])
        : "r"(a[0]), "r"(a[1]), "r"(a[2]), "r"(a[3]), "r"(b[0]), "r"(b[1]));
}
__device__ __forceinline__ void ldsm_x4(uint32_t* r, uint32_t addr) {
    asm volatile("ldmatrix.sync.aligned.m8n8.x4.shared.b16 {%0,%1,%2,%3}, [%4];"
        : "=r"(r[0]), "=r"(r[1]), "=r"(r[2]), "=r"(r[3]) : "r"(addr));
}
__device__ __forceinline__ void ldsm_x2(uint32_t& r0, uint32_t& r1, uint32_t addr) {
    asm volatile("ldmatrix.sync.aligned.m8n8.x2.shared.b16 {%0,%1}, [%2];"
        : "=r"(r0), "=r"(r1) : "r"(addr));
}
#define CP_ASYNC16(sm, gm) asm volatile("cp.async.cg.shared.global [%0], [%1], 16;" :: "r"(sm), "l"(gm))
#define CP_COMMIT()  asm volatile("cp.async.commit_group;" ::: "memory")
#define CP_WAIT0()   asm volatile("cp.async.wait_group 0;" ::: "memory")

// ---------------- 1) x transpose + gap partials ----------------------------------
__global__ void xT_kernel(const float* __restrict__ x) {
    __shared__ float sm[128][33];
    int wblk = blockIdx.x, h = blockIdx.y, b = blockIdx.z;
    int tid = threadIdx.x, lane = tid & 31, w = tid >> 5;
    float vals[16];
    #pragma unroll
    for (int p = 0; p < 16; p++) {
        int c1 = p*8 + w;
        float v = x[(((size_t)b*C1_ + c1)*HH_ + h)*WW_ + wblk*32 + lane];
        sm[c1][lane] = v;
        vals[p] = v;
    }
    #pragma unroll
    for (int p = 0; p < 16; p++) {
        float s = warpReduceSum(vals[p]);
        if (lane == 0)
            g_gpart[(((size_t)b*HH_ + h)*3 + wblk)*C1_ + p*8 + w] = s;
    }
    __syncthreads();
    #pragma unroll
    for (int p = 0; p < 16; p++) {
        int c1 = tid & 127;
        int j  = p*2 + (tid >> 7);
        g_xh[((((size_t)b*HH_ + h)*WW_) + wblk*32 + j)*C1_ + c1] =
            __float2half_rn(sm[c1][j]);
    }
}

// ---------------- 2) gate: gap reduce + softmax + bmix ----------------------------
__global__ void gate_kernel(const float* __restrict__ fc_w,
                            const float* __restrict__ fc_b,
                            const float* __restrict__ bias) {
    int b = blockIdx.x;
    int tid = threadIdx.x;
    __shared__ float sgap[C1_];
    __shared__ float slog[KEXP_];
    __shared__ float sg4[KEXP_];
    float s = 0.f;
    for (int c = 0; c < 288; c++) s += g_gpart[((size_t)b*288 + c)*C1_ + tid];
    sgap[tid] = s * (1.0f / (float)HW_);
    __syncthreads();
    int k = tid >> 5, lane = tid & 31;
    float acc = 0.f;
    #pragma unroll
    for (int r = 0; r < 4; r++)
        acc += sgap[lane*4 + r] * fc_w[k*C1_ + lane*4 + r];
    acc = warpReduceSum(acc);
    if (lane == 0) slog[k] = acc + fc_b[k];
    __syncthreads();
    if (tid == 0) {
        float m = fmaxf(fmaxf(slog[0], slog[1]), fmaxf(slog[2], slog[3]));
        float e0 = expf(slog[0]-m), e1 = expf(slog[1]-m),
              e2 = expf(slog[2]-m), e3 = expf(slog[3]-m);
        float inv = 1.0f / (e0+e1+e2+e3);
        sg4[0] = e0*inv; sg4[1] = e1*inv; sg4[2] = e2*inv; sg4[3] = e3*inv;
    }
    __syncthreads();
    if (tid < KEXP_) g_gate[b*KEXP_ + tid] = sg4[tid];
    float s2 = 0.f;
    #pragma unroll
    for (int kk = 0; kk < KEXP_; kk++) s2 += sg4[kk] * bias[kk*C2_ + tid];
    g_bmix[b*C2_ + tid] = s2;
}

// ---------------- 3) weight mix -> [b][tap][c2][c1] (fp16) --------------------------
__global__ void wmix_kernel(const float* __restrict__ weight) {
    int c2 = blockIdx.x, b = blockIdx.y;
    int c1 = threadIdx.x;
    __shared__ float sg[KEXP_];
    if (threadIdx.x < KEXP_) sg[threadIdx.x] = g_gate[b*KEXP_ + threadIdx.x];
    __syncthreads();
    float acc[9] = {0,0,0,0,0,0,0,0,0};
    #pragma unroll
    for (int k = 0; k < KEXP_; k++) {
        const float* wp = weight + (((size_t)k*C2_ + c2)*C1_ + c1)*9;
        float g = sg[k];
        #pragma unroll
        for (int r = 0; r < 9; r++) acc[r] += g * wp[r];
    }
    #pragma unroll
    for (int r = 0; r < 9; r++)
        g_wh[(((size_t)b*9 + r)*C2_ + c2)*C1_ + c1] = __float2half_rn(acc[r]);
}

// ---------------- 4) conv: 4 h-rows per CTA, ldmatrix + cp.async ---------------------
// pads 136 halves (272 B row stride): 16B-aligned, ldmatrix conflict-free.
#define APAD 136
#define BCOL 136
#define BROW (98*BCOL)                 // halves per staged row
#define A_BYTES (128*APAD*2)           // 34816
#define B_BYTES (6*BROW*2)             // 159936
#define CONV_SMEM (2*A_BYTES + B_BYTES)  // 229568 (sred aliases A buffers)

__device__ __forceinline__ void stage_A(uint32_t sa_u, const __half* wsrc, int tid) {
    #pragma unroll
    for (int p = 0; p < 8; p++) {
        int idx = p*256 + tid;
        int c2 = idx >> 4, e = idx & 15;
        CP_ASYNC16(sa_u + (uint32_t)(c2*APAD + e*8)*2,
                   wsrc + (size_t)c2*C1_ + e*8);
    }
}

__global__ void __launch_bounds__(256, 1)
conv_mma_kernel(float* __restrict__ y) {
    extern __shared__ __half sh[];
    float* sred = (float*)sh;                    // aliases A buffers (dead at epilogue)

    int tid = threadIdx.x, lane = tid & 31, warp = tid >> 5;
    int hg = blockIdx.x, b = blockIdx.y;
    int h0 = hg * 4;
    int i  = warp & 3;            // h row within group
    int mh = warp >> 2;           // M half
    int mbase = mh * 64;
    int gq = lane >> 2, tg = lane & 3;

    uint32_t sbase = smem_u32(sh);
    uint32_t sA_u[2] = { sbase, sbase + A_BYTES };
    uint32_t sB_u = sbase + 2*A_BYTES;
    __half* sB = (__half*)((char*)sh + 2*A_BYTES);

    // kick off A tap 0 + stage all 6 input rows
    stage_A(sA_u[0], g_wh + (size_t)b*9*C2_*C1_, tid);
    CP_COMMIT();
    {
        const __half* xb = g_xh + (size_t)b*HH_*WW_*C1_;
        for (int idx = tid; idx < 6*98*16; idx += 256) {
            int r = idx / (98*16);
            int rem = idx - r*(98*16);
            int col = rem >> 4, e = rem & 15;
            int gh = h0 - 1 + r, gw = col - 1;
            uint4 v = make_uint4(0u,0u,0u,0u);
            if ((unsigned)gh < (unsigned)HH_ && (unsigned)gw < (unsigned)WW_)
                v = *(const uint4*)(xb + ((size_t)gh*WW_ + gw)*C1_ + e*8);
            *(uint4*)(sB + r*BROW + col*BCOL + e*8) = v;
        }
    }

    float d[4][12][4];
    #pragma unroll
    for (int mi = 0; mi < 4; mi++)
        #pragma unroll
        for (int ni = 0; ni < 12; ni++)
            #pragma unroll
            for (int q = 0; q < 4; q++) d[mi][ni][q] = 0.f;

    uint32_t a_lane_off = (uint32_t)(((lane & 15)*APAD) + ((lane >> 4)*8)) * 2;
    uint32_t b_lane_off = (uint32_t)(((lane & 7)*BCOL) + (((lane >> 3) & 1)*8)) * 2;

    CP_WAIT0();
    __syncthreads();

    for (int tap = 0; tap < 9; tap++) {
        int dy = tap / 3, dx = tap - dy*3;
        int cur = tap & 1, nxt = cur ^ 1;
        if (tap < 8)
            stage_A(sA_u[nxt], g_wh + ((size_t)b*9 + tap + 1)*C2_*C1_, tid);
        CP_COMMIT();

        uint32_t abase = sA_u[cur] + (uint32_t)(mbase*APAD)*2 + a_lane_off;
        uint32_t bbase = sB_u + (uint32_t)((i + dy)*BROW + dx*BCOL)*2 + b_lane_off;

        #pragma unroll
        for (int ks = 0; ks < 8; ks++) {
            uint32_t a[4][4];
            #pragma unroll
            for (int mi = 0; mi < 4; mi++)
                ldsm_x4(a[mi], abase + mi*(16*APAD*2) + ks*32);
            #pragma unroll
            for (int ni = 0; ni < 12; ni++) {
                uint32_t bb[2];
                ldsm_x2(bb[0], bb[1], bbase + ni*(8*BCOL*2) + ks*32);
                #pragma unroll
                for (int mi = 0; mi < 4; mi++)
                    mma_f16(d[mi][ni], a[mi], bb);
            }
        }
        CP_WAIT0();
        __syncthreads();
    }

    // epilogue: +bmix, store y, BN partial sums (sred aliases dead A buffers)
    int h = h0 + i;
    #pragma unroll
    for (int mi = 0; mi < 4; mi++) {
        int c2a = mbase + mi*16 + gq;
        int c2b = c2a + 8;
        float bm0 = g_bmix[b*C2_ + c2a];
        float bm1 = g_bmix[b*C2_ + c2b];
        float* rowa = y + (((size_t)b*C2_ + c2a)*HH_ + h)*WW_;
        float* rowb = y + (((size_t)b*C2_ + c2b)*HH_ + h)*WW_;
        float s0=0.f, q0=0.f, s1=0.f, q1=0.f;
        #pragma unroll
        for (int ni = 0; ni < 12; ni++) {
            int n = ni*8 + 2*tg;
            float v0 = d[mi][ni][0] + bm0, v1 = d[mi][ni][1] + bm0;
            float v2 = d[mi][ni][2] + bm1, v3 = d[mi][ni][3] + bm1;
            *(float2*)(rowa + n) = make_float2(v0, v1);
            *(float2*)(rowb + n) = make_float2(v2, v3);
            s0 += v0 + v1; q0 += v0*v0 + v1*v1;
            s1 += v2 + v3; q1 += v2*v2 + v3*v3;
        }
        s0 += __shfl_down_sync(0xffffffffu, s0, 2); s0 += __shfl_down_sync(0xffffffffu, s0, 1);
        q0 += __shfl_down_sync(0xffffffffu, q0, 2); q0 += __shfl_down_sync(0xffffffffu, q0, 1);
        s1 += __shfl_down_sync(0xffffffffu, s1, 2); s1 += __shfl_down_sync(0xffffffffu, s1, 1);
        q1 += __shfl_down_sync(0xffffffffu, q1, 2); q1 += __shfl_down_sync(0xffffffffu, q1, 1);
        if (tg == 0) {
            int base = warp*64 + mi*16;
            sred[base + gq]           = s0;
            sred[base + 8 + gq]       = s1;
            sred[512 + base + gq]     = q0;
            sred[512 + base + 8 + gq] = q1;
        }
    }
    __syncthreads();
    {
        int c2 = tid >> 1, which = tid & 1;
        int mh2 = c2 >> 6, rem = c2 & 63;
        float acc = 0.f;
        #pragma unroll
        for (int r = 0; r < 4; r++)
            acc += sred[which*512 + (mh2*4 + r)*64 + rem];
        g_bnpart[(((size_t)b*24 + hg)*C2_ + c2)*2 + which] = acc;
    }
}

// ---------------- 5) finalize BN ------------------------------------------------------
__global__ void bnfin_kernel(const float* __restrict__ gamma,
                             const float* __restrict__ beta) {
    int c2 = blockIdx.x;
    int tid = threadIdx.x;
    float s = 0.f, q = 0.f;
    for (int idx = tid; idx < B_*24; idx += 256) {
        s += g_bnpart[((size_t)idx*C2_ + c2)*2];
        q += g_bnpart[((size_t)idx*C2_ + c2)*2 + 1];
    }
    s = warpReduceSum(s); q = warpReduceSum(q);
    __shared__ float sms[8], smq[8];
    int lane = tid & 31, w = tid >> 5;
    if (lane == 0) { sms[w] = s; smq[w] = q; }
    __syncthreads();
    if (w == 0) {
        s = (lane < 8) ? sms[lane] : 0.f;
        q = (lane < 8) ? smq[lane] : 0.f;
        s = warpReduceSum(s); q = warpReduceSum(q);
        if (lane == 0) {
            const float n = (float)B_ * (float)HW_;
            float mean = s / n;
            float var  = q / n - mean*mean;
            float inv  = rsqrtf(var + 1e-5f);
            float sc = gamma[c2] * inv;
            g_scale[c2] = sc;
            g_shift[c2] = beta[c2] - mean * sc;
        }
    }
}

// ---------------- 6) BN affine + SiLU --------------------------------------------------
__global__ void act_kernel(float* __restrict__ y) {
    int idx = blockIdx.x * 256 + threadIdx.x;
    const int N4 = (B_*C2_*HW_) / 4;
    if (idx >= N4) return;
    int c2 = (idx / (HW_/4)) & (C2_-1);
    float sc = g_scale[c2], sh = g_shift[c2];
    float4 v = ((const float4*)y)[idx];
    float t;
    t = v.x*sc + sh; v.x = t / (1.f + expf(-t));
    t = v.y*sc + sh; v.y = t / (1.f + expf(-t));
    t = v.z*sc + sh; v.z = t / (1.f + expf(-t));
    t = v.w*sc + sh; v.w = t / (1.f + expf(-t));
    ((float4*)y)[idx] = v;
}

// ---------------- launcher ---------------------------------------------------------------
extern "C" void kernel_launch(void* const* d_in, const int* in_sizes, int n_in,
                              void* d_out, int out_size) {
    const float* x      = (const float*)d_in[0];
    const float* fc_w   = (const float*)d_in[1];
    const float* fc_b   = (const float*)d_in[2];
    const float* weight = (const float*)d_in[3];
    const float* bias   = (const float*)d_in[4];
    const float* gamma  = (const float*)d_in[5];
    const float* beta   = (const float*)d_in[6];
    float* y = (float*)d_out;

    cudaFuncSetAttribute(conv_mma_kernel,
                         cudaFuncAttributeMaxDynamicSharedMemorySize, CONV_SMEM);

    dim3 tgrid(WW_/32, HH_, B_);
    xT_kernel<<<tgrid, 256>>>(x);

    gate_kernel<<<B_, 128>>>(fc_w, fc_b, bias);

    dim3 wgrid(C2_, B_);
    wmix_kernel<<<wgrid, 128>>>(weight);

    dim3 cgrid(24, B_);
    conv_mma_kernel<<<cgrid, 256, CONV_SMEM>>>(y);

    bnfin_kernel<<<C2_, 256>>>(gamma, beta);

    const int N4 = (B_*C2_*HW_) / 4;
    act_kernel<<<(N4 + 255)/256, 256>>>(y);
}